// round 17
// baseline (speedup 1.0000x reference)
#include <cuda_runtime.h>
#include <cuda_bf16.h>
#include <math.h>
#include <stdint.h>

#define NTHREADS 256
#define HIDDEN 256

// Fused sphere-trace + color-MLP renderer. 2 rays per thread (ILP).
//
// TRACE/MASK RECIPE IS BIT-EXACT AGAINST THE REFERENCE — DO NOT TOUCH:
//   LOOP (jitted fori_loop fusion, fully contracted):
//     p = fma(t,d,o); q = p - c; s = fma(qz,qz, fma(qx,qx, rn(qy*qy)));
//     dist = sqrt.rn(s) - r; t += dist   (63 updates)
//   POINTS (eager, plain rn):  p = rn(o + rn(t*d))
//   MASK (eager norm reduce, S5 chain on plain points): hit = dist < 1e-8
// Early-exit safety: exact fixed point (tn==t) -> further updates are
// bit-identical no-ops; dist>8 -> certified miss (dist >= t-4, monotone),
// output zeros regardless of how t evolves afterwards. Hence updates can run
// unconditionally; exit only when BOTH rays are done.

__device__ __forceinline__ uint64_t pack2(float lo, float hi) {
    uint64_t v;
    asm("mov.b64 %0, {%1, %2};" : "=l"(v) : "f"(lo), "f"(hi));
    return v;
}
__device__ __forceinline__ void unpack2(uint64_t v, float& lo, float& hi) {
    asm("mov.b64 {%0, %1}, %2;" : "=f"(lo), "=f"(hi) : "l"(v));
}
__device__ __forceinline__ uint64_t fma2(uint64_t a, uint64_t b, uint64_t c) {
    uint64_t d;
    asm("fma.rn.f32x2 %0, %1, %2, %3;" : "=l"(d) : "l"(a), "l"(b), "l"(c));
    return d;
}

__global__ __launch_bounds__(NTHREADS)
void sphere_mlp_kernel(const float* __restrict__ origins,
                       const float* __restrict__ directions,
                       const float* __restrict__ center,
                       const float* __restrict__ radius,
                       const float* __restrict__ W1,
                       const float* __restrict__ b1,
                       const float* __restrict__ W2,
                       const float* __restrict__ b2,
                       const int*   __restrict__ max_iters,
                       float* __restrict__ out,
                       int N)
{
    // sw1[j] = (W1x[j], W1y[j], W1z[j], b1[j]);  sw2[j] = (W2x[j], W2y[j], W2z[j], 0)
    __shared__ float4 sw1[HIDDEN];
    __shared__ float4 sw2[HIDDEN];
    __shared__ float  sb2[3];

    const int tid = threadIdx.x;
    for (int j = tid; j < HIDDEN; j += NTHREADS) {
        sw1[j] = make_float4(W1[j], W1[HIDDEN + j], W1[2 * HIDDEN + j], b1[j]);
        sw2[j] = make_float4(W2[3 * j + 0], W2[3 * j + 1], W2[3 * j + 2], 0.0f);
    }
    if (tid < 3) sb2[tid] = b2[tid];
    __syncthreads();

    const int gid = blockIdx.x * NTHREADS + tid;
    const int i0 = 2 * gid;
    const int i1 = 2 * gid + 1;
    if (i0 >= N) return;
    const bool have1 = (i1 < N);

    const float cx = center[0], cy = center[1], cz = center[2];
    const float r  = radius[0];
    const int iters = max_iters[0] - 1;   // reference does max_iters-1 updates

    const float ox0 = origins[3 * i0 + 0], oy0 = origins[3 * i0 + 1], oz0 = origins[3 * i0 + 2];
    const float dx0 = directions[3 * i0 + 0], dy0 = directions[3 * i0 + 1], dz0 = directions[3 * i0 + 2];
    const float ox1 = have1 ? origins[3 * i1 + 0] : 0.0f;
    const float oy1 = have1 ? origins[3 * i1 + 1] : 0.0f;
    const float oz1 = have1 ? origins[3 * i1 + 2] : 0.0f;
    const float dx1 = have1 ? directions[3 * i1 + 0] : 0.0f;
    const float dy1 = have1 ? directions[3 * i1 + 1] : 0.0f;
    const float dz1 = have1 ? directions[3 * i1 + 2] : 1.0f;

    // --- interleaved bit-exact trace: two independent chains per thread ---
    float t0 = 0.0f, t1 = 0.0f;
    bool done0 = false, done1 = !have1;
    for (int it = 0; it < iters; ++it) {
        // ray 0
        {
            const float px = fmaf(t0, dx0, ox0);
            const float py = fmaf(t0, dy0, oy0);
            const float pz = fmaf(t0, dz0, oz0);
            const float qx = __fsub_rn(px, cx);
            const float qy = __fsub_rn(py, cy);
            const float qz = __fsub_rn(pz, cz);
            const float s  = fmaf(qz, qz, fmaf(qx, qx, __fmul_rn(qy, qy)));
            const float dist = __fsub_rn(__fsqrt_rn(s), r);
            const float tn = __fadd_rn(t0, dist);
            done0 = done0 || (tn == t0) || (dist > 8.0f);
            t0 = tn;
        }
        // ray 1
        if (have1) {
            const float px = fmaf(t1, dx1, ox1);
            const float py = fmaf(t1, dy1, oy1);
            const float pz = fmaf(t1, dz1, oz1);
            const float qx = __fsub_rn(px, cx);
            const float qy = __fsub_rn(py, cy);
            const float qz = __fsub_rn(pz, cz);
            const float s  = fmaf(qz, qz, fmaf(qx, qx, __fmul_rn(qy, qy)));
            const float dist = __fsub_rn(__fsqrt_rn(s), r);
            const float tn = __fadd_rn(t1, dist);
            done1 = done1 || (tn == t1) || (dist > 8.0f);
            t1 = tn;
        }
        if (done0 && done1) break;
    }

    // --- POINTS (plain rn) + MASK (S5 on plain points), per ray — frozen ---
    const float px0 = __fadd_rn(ox0, __fmul_rn(t0, dx0));
    const float py0 = __fadd_rn(oy0, __fmul_rn(t0, dy0));
    const float pz0 = __fadd_rn(oz0, __fmul_rn(t0, dz0));
    float qx = __fsub_rn(px0, cx), qy = __fsub_rn(py0, cy), qz = __fsub_rn(pz0, cz);
    float s  = fmaf(qz, qz, fmaf(qx, qx, __fmul_rn(qy, qy)));
    const bool hit0 = (__fsub_rn(__fsqrt_rn(s), r) < 1e-8f);

    const float px1 = __fadd_rn(ox1, __fmul_rn(t1, dx1));
    const float py1 = __fadd_rn(oy1, __fmul_rn(t1, dy1));
    const float pz1 = __fadd_rn(oz1, __fmul_rn(t1, dz1));
    qx = __fsub_rn(px1, cx); qy = __fsub_rn(py1, cy); qz = __fsub_rn(pz1, cz);
    s  = fmaf(qz, qz, fmaf(qx, qx, __fmul_rn(qy, qy)));
    const bool hit1 = have1 && (__fsub_rn(__fsqrt_rn(s), r) < 1e-8f);

    if (!hit0 && !hit1) {
        out[3 * i0 + 0] = 0.0f; out[3 * i0 + 1] = 0.0f; out[3 * i0 + 2] = 0.0f;
        if (have1) { out[3 * i1 + 0] = 0.0f; out[3 * i1 + 1] = 0.0f; out[3 * i1 + 2] = 0.0f; }
        return;
    }

    // --- color MLP: both rays in the two f32x2 lanes (one pass serves both) ---
    // Guard non-hit lanes with zeroed coords so no inf/nan pollutes the pipe.
    const float gx0 = hit0 ? px0 : 0.0f, gy0 = hit0 ? py0 : 0.0f, gz0 = hit0 ? pz0 : 0.0f;
    const float gx1 = hit1 ? px1 : 0.0f, gy1 = hit1 ? py1 : 0.0f, gz1 = hit1 ? pz1 : 0.0f;
    const uint64_t PX = pack2(gx0, gx1);
    const uint64_t PY = pack2(gy0, gy1);
    const uint64_t PZ = pack2(gz0, gz1);

    uint64_t A0 = 0, A1 = 0, A2 = 0;   // packed (ray0, ray1) accumulators

#pragma unroll 8
    for (int j = 0; j < HIDDEN; ++j) {
        const float4 w = sw1[j];
        uint64_t h2 = fma2(PX, pack2(w.x, w.x),
                     fma2(PY, pack2(w.y, w.y),
                     fma2(PZ, pack2(w.z, w.z), pack2(w.w, w.w))));
        float h0, h1;
        unpack2(h2, h0, h1);
        h2 = pack2(fmaxf(h0, 0.0f), fmaxf(h1, 0.0f));

        const float4 v = sw2[j];
        A0 = fma2(h2, pack2(v.x, v.x), A0);
        A1 = fma2(h2, pack2(v.y, v.y), A1);
        A2 = fma2(h2, pack2(v.z, v.z), A2);
    }

    float a00, a01, a10, a11, a20, a21;
    unpack2(A0, a00, a01);
    unpack2(A1, a10, a11);
    unpack2(A2, a20, a21);
    const float bb0 = sb2[0], bb1 = sb2[1], bb2 = sb2[2];

    if (hit0) {
        out[3 * i0 + 0] = 1.0f / (1.0f + expf(-(bb0 + a00)));
        out[3 * i0 + 1] = 1.0f / (1.0f + expf(-(bb1 + a10)));
        out[3 * i0 + 2] = 1.0f / (1.0f + expf(-(bb2 + a20)));
    } else {
        out[3 * i0 + 0] = 0.0f; out[3 * i0 + 1] = 0.0f; out[3 * i0 + 2] = 0.0f;
    }
    if (have1) {
        if (hit1) {
            out[3 * i1 + 0] = 1.0f / (1.0f + expf(-(bb0 + a01)));
            out[3 * i1 + 1] = 1.0f / (1.0f + expf(-(bb1 + a11)));
            out[3 * i1 + 2] = 1.0f / (1.0f + expf(-(bb2 + a21)));
        } else {
            out[3 * i1 + 0] = 0.0f; out[3 * i1 + 1] = 0.0f; out[3 * i1 + 2] = 0.0f;
        }
    }
}

extern "C" void kernel_launch(void* const* d_in, const int* in_sizes, int n_in,
                              void* d_out, int out_size) {
    const float* origins    = (const float*)d_in[0];
    const float* directions = (const float*)d_in[1];
    const float* center     = (const float*)d_in[2];
    const float* radius     = (const float*)d_in[3];
    const float* W1         = (const float*)d_in[4];
    const float* b1         = (const float*)d_in[5];
    const float* W2         = (const float*)d_in[6];
    const float* b2         = (const float*)d_in[7];
    const int*   max_iters  = (const int*)d_in[8];
    float* out = (float*)d_out;

    const int N = in_sizes[0] / 3;
    const int nthreads_total = (N + 1) / 2;
    const int blocks = (nthreads_total + NTHREADS - 1) / NTHREADS;
    sphere_mlp_kernel<<<blocks, NTHREADS>>>(origins, directions, center, radius,
                                            W1, b1, W2, b2, max_iters, out, N);
}